// round 8
// baseline (speedup 1.0000x reference)
#include <cuda_runtime.h>
#include <cuda_bf16.h>
#include <cuda_fp16.h>
#include <cstdint>

#define NMAX 50000
#define EMAX 800000
#define RS 132  // FFMA2 tile row stride (128 + 4 pad)

typedef unsigned long long ull;

// ------------------------- static device scratch ---------------------------
__device__ __align__(16) float  g_px[NMAX * 64];          // x @ w1m_top
__device__ __align__(16) __half g_h16[(size_t)EMAX * 64]; // edge pre-BN acts (fp16)
__device__ __align__(16) float  g_hn[NMAX * 64];          // node pre-BN acts
__device__ __align__(16) float  g_S[NMAX * 64];           // scattered relu sums
__device__ float  g_cnt[NMAX];
__device__ float  g_sum_m[64], g_sq_m[64], g_sum_n[64], g_sq_n[64];
__device__ __align__(16) float g_am[64], g_cm[64], g_an[64], g_cn[64];
__device__ __align__(16) float g_Wc[64 * 64];             // w2m @ w1n_bot
__device__ __align__(16) float g_bvec[64];                // b2m @ w1n_bot

// ------------------------- bit-cast helpers --------------------------------
__device__ __forceinline__ uint32_t h2u(__half2 h) {
    return *reinterpret_cast<uint32_t*>(&h);
}
__device__ __forceinline__ __half2 u2h(uint32_t u) {
    return *reinterpret_cast<__half2*>(&u);
}

// ------------------------- f32x2 packed FMA helpers ------------------------
__device__ __forceinline__ ull pk2(float x) {
    ull r; asm("mov.b64 %0, {%1, %1};" : "=l"(r) : "f"(x)); return r;
}
__device__ __forceinline__ void fma2(ull& d, ull a, ull b) {
    asm("fma.rn.f32x2 %0, %1, %2, %0;" : "+l"(d) : "l"(a), "l"(b));
}
__device__ __forceinline__ void unpk(ull v, float& lo, float& hi) {
    asm("mov.b64 {%0, %1}, %2;" : "=f"(lo), "=f"(hi) : "l"(v));
}

// ------------------------- mma.sync helpers --------------------------------
__device__ __forceinline__ uint32_t smem_u32(const void* p) {
    uint32_t a;
    asm("{ .reg .u64 t; cvta.to.shared.u64 t, %1; cvt.u32.u64 %0, t; }"
        : "=r"(a) : "l"(p));
    return a;
}

#define LDSM4(R, ADDR) \
    asm volatile("ldmatrix.sync.aligned.m8n8.x4.shared.b16 {%0,%1,%2,%3}, [%4];" \
        : "=r"((R)[0]), "=r"((R)[1]), "=r"((R)[2]), "=r"((R)[3]) : "r"(ADDR))

#define MMA_F16(D, A, B0, B1) \
    asm volatile("mma.sync.aligned.m16n8k16.row.col.f32.f16.f16.f32 " \
        "{%0,%1,%2,%3}, {%4,%5,%6,%7}, {%8,%9}, {%0,%1,%2,%3};" \
        : "+f"((D)[0]), "+f"((D)[1]), "+f"((D)[2]), "+f"((D)[3]) \
        : "r"((A)[0]), "r"((A)[1]), "r"((A)[2]), "r"((A)[3]), "r"(B0), "r"(B1))

// smem layout for k_edgeA (static, 28672 B total -> 4 CTAs/SM)
// fp16 tiles use row stride 72 halves = 144 B (ldmatrix conflict-free).
#define OFF_B    0        // 64 x 72 fp16  = 9216
#define OFF_A    9216     // 128 x 72 fp16 = 18432 (ends 27648)
#define OFF_HS   9216     // reused after MMA: 128 x 72 fp16 staging
#define OFF_SEND 27648    // int[128]   = 512
#define OFF_RED  28160    // float[128] = 512
#define SMEM_EA  28672

// ------------------------- FFMA2 GEMM tile core (node kernels) -------------
__device__ __forceinline__ void stageT(float* sAT, float4 v, int row, int kq) {
    sAT[(4 * kq + 0) * RS + row] = v.x;
    sAT[(4 * kq + 1) * RS + row] = v.y;
    sAT[(4 * kq + 2) * RS + row] = v.z;
    sAT[(4 * kq + 3) * RS + row] = v.w;
}
__device__ __forceinline__ void mm32(const float* sAT, const float* sW,
                                     int r, int c, ull acc[8][4]) {
#pragma unroll 4
    for (int k = 0; k < 32; ++k) {
        const float4 A0 = *(const float4*)(sAT + k * RS + 8 * r);
        const float4 A1 = *(const float4*)(sAT + k * RS + 8 * r + 4);
        const ulonglong2 Bv0 = *(const ulonglong2*)(sW + k * 64 + 8 * c);
        const ulonglong2 Bv1 = *(const ulonglong2*)(sW + k * 64 + 8 * c + 4);
        float av[8] = {A0.x, A0.y, A0.z, A0.w, A1.x, A1.y, A1.z, A1.w};
#pragma unroll
        for (int i = 0; i < 8; ++i) {
            ull Ad = pk2(av[i]);
            fma2(acc[i][0], Ad, Bv0.x);
            fma2(acc[i][1], Ad, Bv0.y);
            fma2(acc[i][2], Ad, Bv1.x);
            fma2(acc[i][3], Ad, Bv1.y);
        }
    }
}

// ------------------------- k_zero ------------------------------------------
__global__ void k_zero(int N) {
    int i = blockIdx.x * blockDim.x + threadIdx.x;
    if (i < N * 16) ((float4*)g_S)[i] = make_float4(0.f, 0.f, 0.f, 0.f);
    if (i < N) g_cnt[i] = 0.f;
    if (i < 64) { g_sum_m[i] = 0.f; g_sq_m[i] = 0.f; g_sum_n[i] = 0.f; g_sq_n[i] = 0.f; }
}

// ------------------------- k_wc: Wc = w2m @ w1n_bot ------------------------
__global__ void k_wc(const float* __restrict__ w2m, const float* __restrict__ w1n,
                     const float* __restrict__ b2m) {
    __shared__ __align__(16) float sB[64 * 64];
    int tid = threadIdx.x;
    for (int idx = tid; idx < 1024; idx += 256) {
        int k = idx >> 4, cq = idx & 15;
        *(float4*)&sB[k * 64 + cq * 4] = *(const float4*)&w1n[(64 + k) * 64 + cq * 4];
    }
    __syncthreads();
    for (int idx = tid; idx < 4096; idx += 256) {
        int i = idx >> 6, j = idx & 63;
        float s = 0.f;
#pragma unroll 8
        for (int k = 0; k < 64; ++k) s += w2m[i * 64 + k] * sB[k * 64 + j];
        g_Wc[idx] = s;
    }
    if (tid < 64) {
        float s = 0.f;
#pragma unroll 8
        for (int k = 0; k < 64; ++k) s += b2m[k] * sB[k * 64 + tid];
        g_bvec[tid] = s;
    }
}

// ------------------------- k_px: px = x @ w1m_top --------------------------
__global__ __launch_bounds__(128) void k_px(const float* __restrict__ x,
                                            const float* __restrict__ w1m, int N) {
    __shared__ __align__(16) float sAT[32 * RS];
    __shared__ __align__(16) float sW[64 * 64];
    const int tid = threadIdx.x, c = tid & 7, r = tid >> 3;
    const int n0 = blockIdx.x * 128;

    for (int idx = tid; idx < 1024; idx += 128) {
        int k = idx >> 4, cq = idx & 15;
        *(float4*)&sW[k * 64 + cq * 4] = *(const float4*)&w1m[k * 64 + cq * 4];
    }
    ull acc[8][4];
#pragma unroll
    for (int i = 0; i < 8; ++i) { acc[i][0] = 0; acc[i][1] = 0; acc[i][2] = 0; acc[i][3] = 0; }

    for (int half = 0; half < 2; ++half) {
        __syncthreads();
#pragma unroll
        for (int it = 0; it < 8; ++it) {
            int idx = tid + it * 128, row = idx >> 3, kq = idx & 7, n = n0 + row;
            float4 v = make_float4(0.f, 0.f, 0.f, 0.f);
            if (n < N) v = *(const float4*)&x[n * 64 + half * 32 + kq * 4];
            stageT(sAT, v, row, kq);
        }
        __syncthreads();
        mm32(sAT, sW + half * 2048, r, c, acc);
    }
#pragma unroll
    for (int i = 0; i < 8; ++i) {
        int n = n0 + 8 * r + i;
        if (n < N) {
            float h[8];
            unpk(acc[i][0], h[0], h[1]); unpk(acc[i][1], h[2], h[3]);
            unpk(acc[i][2], h[4], h[5]); unpk(acc[i][3], h[6], h[7]);
            *(float4*)&g_px[n * 64 + 8 * c]     = make_float4(h[0], h[1], h[2], h[3]);
            *(float4*)&g_px[n * 64 + 8 * c + 4] = make_float4(h[4], h[5], h[6], h[7]);
        }
    }
}

// ---- k_edgeA: fp16 HMMA GEMM (128-row tiles) + px gather ------------------
// Writes h (fp16) + BN stats. 256 thr / 8 warps, warp w owns M-strip [16w,16w+16).
__global__ __launch_bounds__(256, 4) void k_edgeA(const float* __restrict__ ea,
                                                  const int* __restrict__ ei,
                                                  const float* __restrict__ w1m,
                                                  const float* __restrict__ b1m,
                                                  int E, int ntiles) {
    __shared__ __align__(1024) char smem[SMEM_EA];
    const uint32_t sb = smem_u32(smem);
    const int tid = threadIdx.x, wid = tid >> 5, lane = tid & 31;
    int* sSend = (int*)(smem + OFF_SEND);
    float* sRed = (float*)(smem + OFF_RED);

    // stage B fp16: B[n][k] = w1m[64+k][n], stride 72 halves — once
    for (int idx = tid; idx < 1024; idx += 256) {
        int n = idx & 63, k4 = (idx >> 6) * 4;
        __half2 h01 = __floats2half2_rn(w1m[4096 + (k4 + 0) * 64 + n],
                                        w1m[4096 + (k4 + 1) * 64 + n]);
        __half2 h23 = __floats2half2_rn(w1m[4096 + (k4 + 2) * 64 + n],
                                        w1m[4096 + (k4 + 3) * 64 + n]);
        *(uint2*)(smem + OFF_B + n * 144 + k4 * 2) = make_uint2(h2u(h01), h2u(h23));
    }
    if (tid < 128) sRed[tid] = 0.f;

    const int q = tid & 15;
    const float4 bq = __ldg((const float4*)b1m + q);
    float4 s  = make_float4(0.f, 0.f, 0.f, 0.f);
    float4 s2 = make_float4(0.f, 0.f, 0.f, 0.f);

    // ldmatrix fragment addresses (16-row A strip per warp)
    const int r8 = lane & 7, sel = lane >> 3;
    const uint32_t aBase = sb + (uint32_t)(OFF_A + (wid * 16 + r8 + (sel & 1) * 8) * 144
                                           + ((sel >> 1) * 8) * 2);
    const uint32_t bBase = sb + (uint32_t)(OFF_B + (((sel >> 1) * 8) + r8) * 144
                                           + ((sel & 1) * 8) * 2);
    const int row0 = lane >> 2, c0 = (lane & 3) * 2;

    for (int t = blockIdx.x; t < ntiles; t += gridDim.x) {
        const int e0 = t * 128;
        __syncthreads();  // guard smem reuse across tiles
        if (tid < 128) { int e = e0 + tid; sSend[tid] = (e < E) ? ei[e] : 0; }

        // stage A fp16 (zero-padded): 128 rows x 16 quads, 8 iters
#pragma unroll
        for (int it = 0; it < 8; ++it) {
            int idx = tid + it * 256, row = idx >> 4, kq = idx & 15;
            float4 v = make_float4(0.f, 0.f, 0.f, 0.f);
            if (e0 + row < E) v = *(const float4*)&ea[(size_t)(e0 + row) * 64 + kq * 4];
            *(uint2*)(smem + OFF_A + row * 144 + kq * 8) =
                make_uint2(h2u(__floats2half2_rn(v.x, v.y)),
                           h2u(__floats2half2_rn(v.z, v.w)));
        }
        __syncthreads();

        // MMA: D = A @ B (fp16 in, fp32 acc). 32 MMAs/warp.
        float acc[8][4];
#pragma unroll
        for (int nt = 0; nt < 8; ++nt)
#pragma unroll
            for (int j = 0; j < 4; ++j) acc[nt][j] = 0.f;

#pragma unroll
        for (int kt = 0; kt < 4; ++kt) {
            uint32_t aF[4];
            LDSM4(aF, aBase + kt * 32);
#pragma unroll
            for (int nt2 = 0; nt2 < 4; ++nt2) {
                uint32_t bF[4];
                LDSM4(bF, bBase + nt2 * 2304 + kt * 32);
                MMA_F16(acc[2 * nt2],     aF, bF[0], bF[1]);
                MMA_F16(acc[2 * nt2 + 1], aF, bF[2], bF[3]);
            }
        }
        __syncthreads();  // A tile dead -> HS may overwrite

        // stage acc as fp16 into HS
        {
            int rb = wid * 16 + row0;
#pragma unroll
            for (int nt = 0; nt < 8; ++nt) {
                *(__half2*)(smem + OFF_HS + rb * 144 + (8 * nt + c0) * 2) =
                    __floats2half2_rn(acc[nt][0], acc[nt][1]);
                *(__half2*)(smem + OFF_HS + (rb + 8) * 144 + (8 * nt + c0) * 2) =
                    __floats2half2_rn(acc[nt][2], acc[nt][3]);
            }
        }
        __syncthreads();

        // epilogue: h = gemm + px[send] + b1m ; write fp16 h ; stats
#pragma unroll
        for (int it = 0; it < 8; ++it) {
            int row = (tid >> 4) + it * 16;
            int e = e0 + row;
            if (e < E) {
                int snd = sSend[row];
                float4 p = __ldg((const float4*)g_px + snd * 16 + q);
                uint2 g = *(uint2*)(smem + OFF_HS + row * 144 + q * 8);
                float2 f01 = __half22float2(u2h(g.x));
                float2 f23 = __half22float2(u2h(g.y));
                float h0 = f01.x + p.x + bq.x, h1 = f01.y + p.y + bq.y;
                float h2 = f23.x + p.z + bq.z, h3 = f23.y + p.w + bq.w;
                s.x += h0; s.y += h1; s.z += h2; s.w += h3;
                s2.x += h0 * h0; s2.y += h1 * h1; s2.z += h2 * h2; s2.w += h3 * h3;
                *(uint2*)&g_h16[(size_t)e * 64 + q * 4] =
                    make_uint2(h2u(__floats2half2_rn(h0, h1)),
                               h2u(__floats2half2_rn(h2, h3)));
            }
        }
    }

    // flush BN stats
    __syncthreads();
    atomicAdd(&sRed[q * 4 + 0], s.x);  atomicAdd(&sRed[q * 4 + 1], s.y);
    atomicAdd(&sRed[q * 4 + 2], s.z);  atomicAdd(&sRed[q * 4 + 3], s.w);
    atomicAdd(&sRed[64 + q * 4 + 0], s2.x); atomicAdd(&sRed[64 + q * 4 + 1], s2.y);
    atomicAdd(&sRed[64 + q * 4 + 2], s2.z); atomicAdd(&sRed[64 + q * 4 + 3], s2.w);
    __syncthreads();
    if (tid < 64) {
        atomicAdd(&g_sum_m[tid], sRed[tid]);
        atomicAdd(&g_sq_m[tid], sRed[64 + tid]);
    }
}

// ------------------------- BN coefficient kernels --------------------------
__global__ void k_bnm(const float* __restrict__ gamma, const float* __restrict__ beta,
                      float inv) {
    int j = threadIdx.x;
    float mu = g_sum_m[j] * inv;
    float var = g_sq_m[j] * inv - mu * mu;
    float a = gamma[j] * rsqrtf(var + 1e-5f);
    g_am[j] = a; g_cm[j] = beta[j] - mu * a;
}
__global__ void k_bnn(const float* __restrict__ gamma, const float* __restrict__ beta,
                      float inv) {
    int j = threadIdx.x;
    float mu = g_sum_n[j] * inv;
    float var = g_sq_n[j] * inv - mu * mu;
    float a = gamma[j] * rsqrtf(var + 1e-5f);
    g_an[j] = a; g_cn[j] = beta[j] - mu * a;
}

// ---- k_edgeB: relu(bn(h16)) scatter-add into g_S, count into g_cnt --------
__global__ __launch_bounds__(256) void k_edgeB(const int* __restrict__ ei, int E) {
    int idx = blockIdx.x * 256 + threadIdx.x;
    if (idx >= E * 16) return;
    int e = idx >> 4, q = idx & 15;
    uint2 g = *(const uint2*)&g_h16[(size_t)e * 64 + q * 4];
    float2 f01 = __half22float2(u2h(g.x));
    float2 f23 = __half22float2(u2h(g.y));
    float4 a = *(const float4*)&g_am[q * 4];
    float4 c = *(const float4*)&g_cm[q * 4];
    float v0 = fmaxf(fmaf(a.x, f01.x, c.x), 0.f);
    float v1 = fmaxf(fmaf(a.y, f01.y, c.y), 0.f);
    float v2 = fmaxf(fmaf(a.z, f23.x, c.z), 0.f);
    float v3 = fmaxf(fmaf(a.w, f23.y, c.w), 0.f);
    int rec = ei[E + e];
    float* dst = &g_S[rec * 64 + q * 4];
    asm volatile("red.global.add.v4.f32 [%0], {%1,%2,%3,%4};"
                 :: "l"(dst), "f"(v0), "f"(v1), "f"(v2), "f"(v3) : "memory");
    if (q == 0) atomicAdd(&g_cnt[rec], 1.f);
}

// ---- k_node1: h_n = x@w1n_top + (S/cnt')@Wc + b1n + [cnt>0]*bvec ----------
__global__ __launch_bounds__(128) void k_node1(const float* __restrict__ x,
                                               const float* __restrict__ w1n,
                                               const float* __restrict__ b1n, int N) {
    __shared__ __align__(16) float sAT[32 * RS];
    __shared__ __align__(16) float sW[64 * 64];
    __shared__ float sSum[64], sSq[64];
    const int tid = threadIdx.x, c = tid & 7, r = tid >> 3;
    const int n0 = blockIdx.x * 128;
    if (tid < 64) { sSum[tid] = 0.f; sSq[tid] = 0.f; }

    ull acc[8][4];
#pragma unroll
    for (int i = 0; i < 8; ++i) { acc[i][0] = 0; acc[i][1] = 0; acc[i][2] = 0; acc[i][3] = 0; }

    for (int ph = 0; ph < 2; ++ph) {
        __syncthreads();
        for (int idx = tid; idx < 1024; idx += 128) {
            int k = idx >> 4, cq = idx & 15;
            *(float4*)&sW[k * 64 + cq * 4] = (ph == 0)
                ? *(const float4*)&w1n[k * 64 + cq * 4]
                : *(const float4*)&g_Wc[k * 64 + cq * 4];
        }
        for (int half = 0; half < 2; ++half) {
            __syncthreads();
#pragma unroll
            for (int it = 0; it < 8; ++it) {
                int idx = tid + it * 128, row = idx >> 3, kq = idx & 7, n = n0 + row;
                float4 v = make_float4(0.f, 0.f, 0.f, 0.f);
                if (n < N) {
                    if (ph == 0) {
                        v = *(const float4*)&x[n * 64 + half * 32 + kq * 4];
                    } else {
                        v = *(const float4*)&g_S[n * 64 + half * 32 + kq * 4];
                        float inv = 1.f / fmaxf(g_cnt[n], 1.f);
                        v.x *= inv; v.y *= inv; v.z *= inv; v.w *= inv;
                    }
                }
                stageT(sAT, v, row, kq);
            }
            __syncthreads();
            mm32(sAT, sW + half * 2048, r, c, acc);
        }
    }

    const float4 bb0 = *(const float4*)&b1n[8 * c];
    const float4 bb1 = *(const float4*)&b1n[8 * c + 4];
    const float4 bv0 = *(const float4*)&g_bvec[8 * c];
    const float4 bv1 = *(const float4*)&g_bvec[8 * c + 4];
    float ls[8], lq[8];
#pragma unroll
    for (int j = 0; j < 8; ++j) { ls[j] = 0.f; lq[j] = 0.f; }

#pragma unroll
    for (int i = 0; i < 8; ++i) {
        int n = n0 + 8 * r + i;
        if (n < N) {
            float ind = (g_cnt[n] > 0.f) ? 1.f : 0.f;
            float h[8];
            unpk(acc[i][0], h[0], h[1]); unpk(acc[i][1], h[2], h[3]);
            unpk(acc[i][2], h[4], h[5]); unpk(acc[i][3], h[6], h[7]);
            h[0] += bb0.x + ind * bv0.x; h[1] += bb0.y + ind * bv0.y;
            h[2] += bb0.z + ind * bv0.z; h[3] += bb0.w + ind * bv0.w;
            h[4] += bb1.x + ind * bv1.x; h[5] += bb1.y + ind * bv1.y;
            h[6] += bb1.z + ind * bv1.z; h[7] += bb1.w + ind * bv1.w;
            *(float4*)&g_hn[n * 64 + 8 * c]     = make_float4(h[0], h[1], h[2], h[3]);
            *(float4*)&g_hn[n * 64 + 8 * c + 4] = make_float4(h[4], h[5], h[6], h[7]);
#pragma unroll
            for (int j = 0; j < 8; ++j) { ls[j] += h[j]; lq[j] += h[j] * h[j]; }
        }
    }
#pragma unroll
    for (int j = 0; j < 8; ++j) {
        atomicAdd(&sSum[8 * c + j], ls[j]);
        atomicAdd(&sSq[8 * c + j], lq[j]);
    }
    __syncthreads();
    if (tid < 64) {
        atomicAdd(&g_sum_n[tid], sSum[tid]);
        atomicAdd(&g_sq_n[tid], sSq[tid]);
    }
}

// ---- k_node2: out = relu(bn(h_n)) @ w2n + b2n -----------------------------
__global__ __launch_bounds__(128) void k_node2(const float* __restrict__ w2n,
                                               const float* __restrict__ b2n,
                                               float* __restrict__ out, int N) {
    __shared__ __align__(16) float sAT[32 * RS];
    __shared__ __align__(16) float sW[64 * 64];
    const int tid = threadIdx.x, c = tid & 7, r = tid >> 3;
    const int n0 = blockIdx.x * 128;

    for (int idx = tid; idx < 1024; idx += 128) {
        int k = idx >> 4, cq = idx & 15;
        *(float4*)&sW[k * 64 + cq * 4] = *(const float4*)&w2n[k * 64 + cq * 4];
    }
    ull acc[8][4];
#pragma unroll
    for (int i = 0; i < 8; ++i) { acc[i][0] = 0; acc[i][1] = 0; acc[i][2] = 0; acc[i][3] = 0; }

    for (int half = 0; half < 2; ++half) {
        __syncthreads();
#pragma unroll
        for (int it = 0; it < 8; ++it) {
            int idx = tid + it * 128, row = idx >> 3, kq = idx & 7, n = n0 + row;
            float4 v = make_float4(0.f, 0.f, 0.f, 0.f);
            if (n < N) {
                int kb = half * 32 + kq * 4;
                float4 h = *(const float4*)&g_hn[n * 64 + kb];
                float4 a = *(const float4*)&g_an[kb];
                float4 cc = *(const float4*)&g_cn[kb];
                v.x = fmaxf(fmaf(a.x, h.x, cc.x), 0.f);
                v.y = fmaxf(fmaf(a.y, h.y, cc.y), 0.f);
                v.z = fmaxf(fmaf(a.z, h.z, cc.z), 0.f);
                v.w = fmaxf(fmaf(a.w, h.w, cc.w), 0.f);
            }
            stageT(sAT, v, row, kq);
        }
        __syncthreads();
        mm32(sAT, sW + half * 2048, r, c, acc);
    }
    const float4 bb0 = *(const float4*)&b2n[8 * c];
    const float4 bb1 = *(const float4*)&b2n[8 * c + 4];
#pragma unroll
    for (int i = 0; i < 8; ++i) {
        int n = n0 + 8 * r + i;
        if (n < N) {
            float h[8];
            unpk(acc[i][0], h[0], h[1]); unpk(acc[i][1], h[2], h[3]);
            unpk(acc[i][2], h[4], h[5]); unpk(acc[i][3], h[6], h[7]);
            *(float4*)&out[n * 64 + 8 * c] =
                make_float4(h[0] + bb0.x, h[1] + bb0.y, h[2] + bb0.z, h[3] + bb0.w);
            *(float4*)&out[n * 64 + 8 * c + 4] =
                make_float4(h[4] + bb1.x, h[5] + bb1.y, h[6] + bb1.z, h[7] + bb1.w);
        }
    }
}

// ------------------------- launch ------------------------------------------
extern "C" void kernel_launch(void* const* d_in, const int* in_sizes, int n_in,
                              void* d_out, int out_size) {
    const float* x       = (const float*)d_in[0];
    const int*   ei      = (const int*)d_in[1];
    const float* ea      = (const float*)d_in[2];
    const float* w1m     = (const float*)d_in[5];
    const float* b1m     = (const float*)d_in[6];
    const float* gamma_m = (const float*)d_in[7];
    const float* beta_m  = (const float*)d_in[8];
    const float* w2m     = (const float*)d_in[9];
    const float* b2m     = (const float*)d_in[10];
    const float* w1n     = (const float*)d_in[11];
    const float* b1n     = (const float*)d_in[12];
    const float* gamma_n = (const float*)d_in[13];
    const float* beta_n  = (const float*)d_in[14];
    const float* w2n     = (const float*)d_in[15];
    const float* b2n     = (const float*)d_in[16];
    float* out = (float*)d_out;

    const int N = in_sizes[0] / 64;
    const int E = in_sizes[2] / 64;
    const int nb = (N + 127) / 128;
    const int ntiles = (E + 127) / 128;
    const int grid_e = ntiles < 592 ? ntiles : 592;

    k_zero<<<(N * 16 + 255) / 256, 256>>>(N);
    k_wc<<<1, 256>>>(w2m, w1n, b2m);
    k_px<<<nb, 128>>>(x, w1m, N);
    k_edgeA<<<grid_e, 256>>>(ea, ei, w1m, b1m, E, ntiles);
    k_bnm<<<1, 64>>>(gamma_m, beta_m, 1.f / (float)E);
    k_edgeB<<<(E * 16 + 255) / 256, 256>>>(ei, E);
    k_node1<<<nb, 128>>>(x, w1n, b1n, N);
    k_bnn<<<1, 64>>>(gamma_n, beta_n, 1.f / (float)N);
    k_node2<<<nb, 128>>>(w2n, b2n, out, N);
}

// round 9
// speedup vs baseline: 1.2949x; 1.2949x over previous
#include <cuda_runtime.h>
#include <cuda_bf16.h>
#include <cuda_fp16.h>
#include <cstdint>

#define NMAX 50000
#define EMAX 800000
#define RS 132  // FFMA2 tile row stride (128 + 4 pad)

typedef unsigned long long ull;

// ------------------------- static device scratch ---------------------------
__device__ __align__(16) float  g_px[NMAX * 64];          // x @ w1m_top
__device__ __align__(16) __half g_h16[(size_t)EMAX * 64]; // edge pre-BN acts (fp16)
__device__ __align__(16) float  g_hn[NMAX * 64];          // node pre-BN acts
__device__ __align__(16) float  g_S[NMAX * 64];           // scattered relu sums
__device__ float  g_cnt[NMAX];
__device__ float  g_sum_m[64], g_sq_m[64], g_sum_n[64], g_sq_n[64];
__device__ __align__(16) float g_am[64], g_cm[64], g_an[64], g_cn[64];
__device__ __align__(16) float g_Wc[64 * 64];             // w2m @ w1n_bot
__device__ __align__(16) float g_bvec[64];                // b2m @ w1n_bot

// ------------------------- bit-cast helpers --------------------------------
__device__ __forceinline__ uint32_t h2u(__half2 h) {
    return *reinterpret_cast<uint32_t*>(&h);
}
__device__ __forceinline__ __half2 u2h(uint32_t u) {
    return *reinterpret_cast<__half2*>(&u);
}

// ------------------------- f32x2 packed FMA helpers ------------------------
__device__ __forceinline__ ull pk2(float x) {
    ull r; asm("mov.b64 %0, {%1, %1};" : "=l"(r) : "f"(x)); return r;
}
__device__ __forceinline__ void fma2(ull& d, ull a, ull b) {
    asm("fma.rn.f32x2 %0, %1, %2, %0;" : "+l"(d) : "l"(a), "l"(b));
}
__device__ __forceinline__ void unpk(ull v, float& lo, float& hi) {
    asm("mov.b64 {%0, %1}, %2;" : "=f"(lo), "=f"(hi) : "l"(v));
}

// ------------------------- mma.sync helpers --------------------------------
__device__ __forceinline__ uint32_t smem_u32(const void* p) {
    uint32_t a;
    asm("{ .reg .u64 t; cvta.to.shared.u64 t, %1; cvt.u32.u64 %0, t; }"
        : "=r"(a) : "l"(p));
    return a;
}

#define LDSM4(R, ADDR) \
    asm volatile("ldmatrix.sync.aligned.m8n8.x4.shared.b16 {%0,%1,%2,%3}, [%4];" \
        : "=r"((R)[0]), "=r"((R)[1]), "=r"((R)[2]), "=r"((R)[3]) : "r"(ADDR))

#define MMA_F16(D, A, B0, B1) \
    asm volatile("mma.sync.aligned.m16n8k16.row.col.f32.f16.f16.f32 " \
        "{%0,%1,%2,%3}, {%4,%5,%6,%7}, {%8,%9}, {%0,%1,%2,%3};" \
        : "+f"((D)[0]), "+f"((D)[1]), "+f"((D)[2]), "+f"((D)[3]) \
        : "r"((A)[0]), "r"((A)[1]), "r"((A)[2]), "r"((A)[3]), "r"(B0), "r"(B1))

// smem layout for k_edgeA (dynamic): total 47616 B (< 48KB default limit)
// fp16 tiles use row stride 72 halves = 144 B (ldmatrix conflict-free).
#define OFF_B    0        // 64 x 72 fp16 = 9216
#define OFF_SEND 9216     // int[256]   = 1024
#define OFF_RED  10240    // float[128] = 512
#define OFF_AH   10752    // 256 x 72 fp16 = 36864 (ends 47616)
#define OFF_HS   10752    // reused after MMA: 256 x 72 fp16 staging
#define SMEM_EA  47616

// ------------------------- FFMA2 GEMM tile core (node kernels) -------------
__device__ __forceinline__ void stageT(float* sAT, float4 v, int row, int kq) {
    sAT[(4 * kq + 0) * RS + row] = v.x;
    sAT[(4 * kq + 1) * RS + row] = v.y;
    sAT[(4 * kq + 2) * RS + row] = v.z;
    sAT[(4 * kq + 3) * RS + row] = v.w;
}
__device__ __forceinline__ void mm32(const float* sAT, const float* sW,
                                     int r, int c, ull acc[8][4]) {
#pragma unroll 4
    for (int k = 0; k < 32; ++k) {
        const float4 A0 = *(const float4*)(sAT + k * RS + 8 * r);
        const float4 A1 = *(const float4*)(sAT + k * RS + 8 * r + 4);
        const ulonglong2 Bv0 = *(const ulonglong2*)(sW + k * 64 + 8 * c);
        const ulonglong2 Bv1 = *(const ulonglong2*)(sW + k * 64 + 8 * c + 4);
        float av[8] = {A0.x, A0.y, A0.z, A0.w, A1.x, A1.y, A1.z, A1.w};
#pragma unroll
        for (int i = 0; i < 8; ++i) {
            ull Ad = pk2(av[i]);
            fma2(acc[i][0], Ad, Bv0.x);
            fma2(acc[i][1], Ad, Bv0.y);
            fma2(acc[i][2], Ad, Bv1.x);
            fma2(acc[i][3], Ad, Bv1.y);
        }
    }
}

// ------------------------- k_zero ------------------------------------------
__global__ void k_zero(int N) {
    int i = blockIdx.x * blockDim.x + threadIdx.x;
    if (i < N * 16) ((float4*)g_S)[i] = make_float4(0.f, 0.f, 0.f, 0.f);
    if (i < N) g_cnt[i] = 0.f;
    if (i < 64) { g_sum_m[i] = 0.f; g_sq_m[i] = 0.f; g_sum_n[i] = 0.f; g_sq_n[i] = 0.f; }
}

// ------------------------- k_wc: Wc = w2m @ w1n_bot ------------------------
__global__ void k_wc(const float* __restrict__ w2m, const float* __restrict__ w1n,
                     const float* __restrict__ b2m) {
    __shared__ __align__(16) float sB[64 * 64];
    int tid = threadIdx.x;
    for (int idx = tid; idx < 1024; idx += 256) {
        int k = idx >> 4, cq = idx & 15;
        *(float4*)&sB[k * 64 + cq * 4] = *(const float4*)&w1n[(64 + k) * 64 + cq * 4];
    }
    __syncthreads();
    for (int idx = tid; idx < 4096; idx += 256) {
        int i = idx >> 6, j = idx & 63;
        float s = 0.f;
#pragma unroll 8
        for (int k = 0; k < 64; ++k) s += w2m[i * 64 + k] * sB[k * 64 + j];
        g_Wc[idx] = s;
    }
    if (tid < 64) {
        float s = 0.f;
#pragma unroll 8
        for (int k = 0; k < 64; ++k) s += b2m[k] * sB[k * 64 + tid];
        g_bvec[tid] = s;
    }
}

// ------------------------- k_px: px = x @ w1m_top --------------------------
__global__ __launch_bounds__(128) void k_px(const float* __restrict__ x,
                                            const float* __restrict__ w1m, int N) {
    __shared__ __align__(16) float sAT[32 * RS];
    __shared__ __align__(16) float sW[64 * 64];
    const int tid = threadIdx.x, c = tid & 7, r = tid >> 3;
    const int n0 = blockIdx.x * 128;

    for (int idx = tid; idx < 1024; idx += 128) {
        int k = idx >> 4, cq = idx & 15;
        *(float4*)&sW[k * 64 + cq * 4] = *(const float4*)&w1m[k * 64 + cq * 4];
    }
    ull acc[8][4];
#pragma unroll
    for (int i = 0; i < 8; ++i) { acc[i][0] = 0; acc[i][1] = 0; acc[i][2] = 0; acc[i][3] = 0; }

    for (int half = 0; half < 2; ++half) {
        __syncthreads();
#pragma unroll
        for (int it = 0; it < 8; ++it) {
            int idx = tid + it * 128, row = idx >> 3, kq = idx & 7, n = n0 + row;
            float4 v = make_float4(0.f, 0.f, 0.f, 0.f);
            if (n < N) v = *(const float4*)&x[n * 64 + half * 32 + kq * 4];
            stageT(sAT, v, row, kq);
        }
        __syncthreads();
        mm32(sAT, sW + half * 2048, r, c, acc);
    }
#pragma unroll
    for (int i = 0; i < 8; ++i) {
        int n = n0 + 8 * r + i;
        if (n < N) {
            float h[8];
            unpk(acc[i][0], h[0], h[1]); unpk(acc[i][1], h[2], h[3]);
            unpk(acc[i][2], h[4], h[5]); unpk(acc[i][3], h[6], h[7]);
            *(float4*)&g_px[n * 64 + 8 * c]     = make_float4(h[0], h[1], h[2], h[3]);
            *(float4*)&g_px[n * 64 + 8 * c + 4] = make_float4(h[4], h[5], h[6], h[7]);
        }
    }
}

// ---- k_edgeA: fp16 HMMA GEMM (256-row tiles) + px gather ------------------
// Writes h (fp16) + BN stats. 256 thr / 8 warps, warp w owns M-strip [32w,32w+32).
__global__ __launch_bounds__(256, 3) void k_edgeA(const float* __restrict__ ea,
                                                  const int* __restrict__ ei,
                                                  const float* __restrict__ w1m,
                                                  const float* __restrict__ b1m,
                                                  int E, int ntiles) {
    extern __shared__ __align__(1024) char smem[];
    const uint32_t sb = smem_u32(smem);
    const int tid = threadIdx.x, wid = tid >> 5, lane = tid & 31;
    int* sSend = (int*)(smem + OFF_SEND);
    float* sRed = (float*)(smem + OFF_RED);

    // stage B fp16: B[n][k] = w1m[64+k][n], stride 72 halves — once
    for (int idx = tid; idx < 1024; idx += 256) {
        int n = idx & 63, k4 = (idx >> 6) * 4;
        __half2 h01 = __floats2half2_rn(w1m[4096 + (k4 + 0) * 64 + n],
                                        w1m[4096 + (k4 + 1) * 64 + n]);
        __half2 h23 = __floats2half2_rn(w1m[4096 + (k4 + 2) * 64 + n],
                                        w1m[4096 + (k4 + 3) * 64 + n]);
        *(uint2*)(smem + OFF_B + n * 144 + k4 * 2) = make_uint2(h2u(h01), h2u(h23));
    }
    if (tid < 128) sRed[tid] = 0.f;

    const int q = tid & 15;
    const float4 bq = __ldg((const float4*)b1m + q);
    float4 s  = make_float4(0.f, 0.f, 0.f, 0.f);
    float4 s2 = make_float4(0.f, 0.f, 0.f, 0.f);

    // ldmatrix fragment addresses (32-row A strip per warp)
    const int r8 = lane & 7, sel = lane >> 3;
    const uint32_t aBase = sb + (uint32_t)(OFF_AH + (wid * 32 + r8 + (sel & 1) * 8) * 144
                                           + ((sel >> 1) * 8) * 2);
    const uint32_t bBase = sb + (uint32_t)(OFF_B + (((sel >> 1) * 8) + r8) * 144
                                           + ((sel & 1) * 8) * 2);
    const int row0 = lane >> 2, c0 = (lane & 3) * 2;

    for (int t = blockIdx.x; t < ntiles; t += gridDim.x) {
        const int e0 = t * 256;
        __syncthreads();  // guard smem reuse across tiles
        { int e = e0 + tid; sSend[tid] = (e < E) ? ei[e] : 0; }

        // stage A fp16 (zero-padded): 256 rows x 16 quads, 16 iters
#pragma unroll
        for (int it = 0; it < 16; ++it) {
            int idx = tid + it * 256, row = idx >> 4, kq = idx & 15;
            float4 v = make_float4(0.f, 0.f, 0.f, 0.f);
            if (e0 + row < E) v = *(const float4*)&ea[(size_t)(e0 + row) * 64 + kq * 4];
            *(uint2*)(smem + OFF_AH + row * 144 + kq * 8) =
                make_uint2(h2u(__floats2half2_rn(v.x, v.y)),
                           h2u(__floats2half2_rn(v.z, v.w)));
        }
        __syncthreads();

        // MMA: D = A @ B (fp16 in, fp32 acc). 64 MMAs/warp.
        float acc[2][8][4];
#pragma unroll
        for (int mt = 0; mt < 2; ++mt)
#pragma unroll
            for (int nt = 0; nt < 8; ++nt)
#pragma unroll
                for (int j = 0; j < 4; ++j) acc[mt][nt][j] = 0.f;

#pragma unroll
        for (int kt = 0; kt < 4; ++kt) {
            uint32_t aF[2][4];
            LDSM4(aF[0], aBase + kt * 32);
            LDSM4(aF[1], aBase + 2304 + kt * 32);
#pragma unroll
            for (int nt2 = 0; nt2 < 4; ++nt2) {
                uint32_t bF[4];
                LDSM4(bF, bBase + nt2 * 2304 + kt * 32);
#pragma unroll
                for (int mt = 0; mt < 2; ++mt) {
                    MMA_F16(acc[mt][2 * nt2],     aF[mt], bF[0], bF[1]);
                    MMA_F16(acc[mt][2 * nt2 + 1], aF[mt], bF[2], bF[3]);
                }
            }
        }
        __syncthreads();  // A tile dead -> HS may overwrite

        // stage acc as fp16 into HS
#pragma unroll
        for (int mt = 0; mt < 2; ++mt) {
            int rb = wid * 32 + mt * 16 + row0;
#pragma unroll
            for (int nt = 0; nt < 8; ++nt) {
                *(__half2*)(smem + OFF_HS + rb * 144 + (8 * nt + c0) * 2) =
                    __floats2half2_rn(acc[mt][nt][0], acc[mt][nt][1]);
                *(__half2*)(smem + OFF_HS + (rb + 8) * 144 + (8 * nt + c0) * 2) =
                    __floats2half2_rn(acc[mt][nt][2], acc[mt][nt][3]);
            }
        }
        __syncthreads();

        // epilogue: h = gemm + px[send] + b1m ; write fp16 h ; stats
#pragma unroll
        for (int it = 0; it < 16; ++it) {
            int row = (tid >> 4) + it * 16;
            int e = e0 + row;
            if (e < E) {
                int snd = sSend[row];
                float4 p = __ldg((const float4*)g_px + snd * 16 + q);
                uint2 g = *(uint2*)(smem + OFF_HS + row * 144 + q * 8);
                float2 f01 = __half22float2(u2h(g.x));
                float2 f23 = __half22float2(u2h(g.y));
                float h0 = f01.x + p.x + bq.x, h1 = f01.y + p.y + bq.y;
                float h2 = f23.x + p.z + bq.z, h3 = f23.y + p.w + bq.w;
                s.x += h0; s.y += h1; s.z += h2; s.w += h3;
                s2.x += h0 * h0; s2.y += h1 * h1; s2.z += h2 * h2; s2.w += h3 * h3;
                *(uint2*)&g_h16[(size_t)e * 64 + q * 4] =
                    make_uint2(h2u(__floats2half2_rn(h0, h1)),
                               h2u(__floats2half2_rn(h2, h3)));
            }
        }
    }

    // flush BN stats
    __syncthreads();
    atomicAdd(&sRed[q * 4 + 0], s.x);  atomicAdd(&sRed[q * 4 + 1], s.y);
    atomicAdd(&sRed[q * 4 + 2], s.z);  atomicAdd(&sRed[q * 4 + 3], s.w);
    atomicAdd(&sRed[64 + q * 4 + 0], s2.x); atomicAdd(&sRed[64 + q * 4 + 1], s2.y);
    atomicAdd(&sRed[64 + q * 4 + 2], s2.z); atomicAdd(&sRed[64 + q * 4 + 3], s2.w);
    __syncthreads();
    if (tid < 64) {
        atomicAdd(&g_sum_m[tid], sRed[tid]);
        atomicAdd(&g_sq_m[tid], sRed[64 + tid]);
    }
}

// ------------------------- BN coefficient kernels --------------------------
__global__ void k_bnm(const float* __restrict__ gamma, const float* __restrict__ beta,
                      float inv) {
    int j = threadIdx.x;
    float mu = g_sum_m[j] * inv;
    float var = g_sq_m[j] * inv - mu * mu;
    float a = gamma[j] * rsqrtf(var + 1e-5f);
    g_am[j] = a; g_cm[j] = beta[j] - mu * a;
}
__global__ void k_bnn(const float* __restrict__ gamma, const float* __restrict__ beta,
                      float inv) {
    int j = threadIdx.x;
    float mu = g_sum_n[j] * inv;
    float var = g_sq_n[j] * inv - mu * mu;
    float a = gamma[j] * rsqrtf(var + 1e-5f);
    g_an[j] = a; g_cn[j] = beta[j] - mu * a;
}

// ---- k_edgeB: relu(bn(h16)) scatter-add into g_S, count into g_cnt --------
__global__ __launch_bounds__(256) void k_edgeB(const int* __restrict__ ei, int E) {
    int idx = blockIdx.x * 256 + threadIdx.x;
    if (idx >= E * 16) return;
    int e = idx >> 4, q = idx & 15;
    uint2 g = *(const uint2*)&g_h16[(size_t)e * 64 + q * 4];
    float2 f01 = __half22float2(u2h(g.x));
    float2 f23 = __half22float2(u2h(g.y));
    float4 a = *(const float4*)&g_am[q * 4];
    float4 c = *(const float4*)&g_cm[q * 4];
    float v0 = fmaxf(fmaf(a.x, f01.x, c.x), 0.f);
    float v1 = fmaxf(fmaf(a.y, f01.y, c.y), 0.f);
    float v2 = fmaxf(fmaf(a.z, f23.x, c.z), 0.f);
    float v3 = fmaxf(fmaf(a.w, f23.y, c.w), 0.f);
    int rec = ei[E + e];
    float* dst = &g_S[rec * 64 + q * 4];
    asm volatile("red.global.add.v4.f32 [%0], {%1,%2,%3,%4};"
                 :: "l"(dst), "f"(v0), "f"(v1), "f"(v2), "f"(v3) : "memory");
    if (q == 0) atomicAdd(&g_cnt[rec], 1.f);
}

// ---- k_node1: h_n = x@w1n_top + (S/cnt')@Wc + b1n + [cnt>0]*bvec ----------
__global__ __launch_bounds__(128) void k_node1(const float* __restrict__ x,
                                               const float* __restrict__ w1n,
                                               const float* __restrict__ b1n, int N) {
    __shared__ __align__(16) float sAT[32 * RS];
    __shared__ __align__(16) float sW[64 * 64];
    __shared__ float sSum[64], sSq[64];
    const int tid = threadIdx.x, c = tid & 7, r = tid >> 3;
    const int n0 = blockIdx.x * 128;
    if (tid < 64) { sSum[tid] = 0.f; sSq[tid] = 0.f; }

    ull acc[8][4];
#pragma unroll
    for (int i = 0; i < 8; ++i) { acc[i][0] = 0; acc[i][1] = 0; acc[i][2] = 0; acc[i][3] = 0; }

    for (int ph = 0; ph < 2; ++ph) {
        __syncthreads();
        for (int idx = tid; idx < 1024; idx += 128) {
            int k = idx >> 4, cq = idx & 15;
            *(float4*)&sW[k * 64 + cq * 4] = (ph == 0)
                ? *(const float4*)&w1n[k * 64 + cq * 4]
                : *(const float4*)&g_Wc[k * 64 + cq * 4];
        }
        for (int half = 0; half < 2; ++half) {
            __syncthreads();
#pragma unroll
            for (int it = 0; it < 8; ++it) {
                int idx = tid + it * 128, row = idx >> 3, kq = idx & 7, n = n0 + row;
                float4 v = make_float4(0.f, 0.f, 0.f, 0.f);
                if (n < N) {
                    if (ph == 0) {
                        v = *(const float4*)&x[n * 64 + half * 32 + kq * 4];
                    } else {
                        v = *(const float4*)&g_S[n * 64 + half * 32 + kq * 4];
                        float inv = 1.f / fmaxf(g_cnt[n], 1.f);
                        v.x *= inv; v.y *= inv; v.z *= inv; v.w *= inv;
                    }
                }
                stageT(sAT, v, row, kq);
            }
            __syncthreads();
            mm32(sAT, sW + half * 2048, r, c, acc);
        }
    }

    const float4 bb0 = *(const float4*)&b1n[8 * c];
    const float4 bb1 = *(const float4*)&b1n[8 * c + 4];
    const float4 bv0 = *(const float4*)&g_bvec[8 * c];
    const float4 bv1 = *(const float4*)&g_bvec[8 * c + 4];
    float ls[8], lq[8];
#pragma unroll
    for (int j = 0; j < 8; ++j) { ls[j] = 0.f; lq[j] = 0.f; }

#pragma unroll
    for (int i = 0; i < 8; ++i) {
        int n = n0 + 8 * r + i;
        if (n < N) {
            float ind = (g_cnt[n] > 0.f) ? 1.f : 0.f;
            float h[8];
            unpk(acc[i][0], h[0], h[1]); unpk(acc[i][1], h[2], h[3]);
            unpk(acc[i][2], h[4], h[5]); unpk(acc[i][3], h[6], h[7]);
            h[0] += bb0.x + ind * bv0.x; h[1] += bb0.y + ind * bv0.y;
            h[2] += bb0.z + ind * bv0.z; h[3] += bb0.w + ind * bv0.w;
            h[4] += bb1.x + ind * bv1.x; h[5] += bb1.y + ind * bv1.y;
            h[6] += bb1.z + ind * bv1.z; h[7] += bb1.w + ind * bv1.w;
            *(float4*)&g_hn[n * 64 + 8 * c]     = make_float4(h[0], h[1], h[2], h[3]);
            *(float4*)&g_hn[n * 64 + 8 * c + 4] = make_float4(h[4], h[5], h[6], h[7]);
#pragma unroll
            for (int j = 0; j < 8; ++j) { ls[j] += h[j]; lq[j] += h[j] * h[j]; }
        }
    }
#pragma unroll
    for (int j = 0; j < 8; ++j) {
        atomicAdd(&sSum[8 * c + j], ls[j]);
        atomicAdd(&sSq[8 * c + j], lq[j]);
    }
    __syncthreads();
    if (tid < 64) {
        atomicAdd(&g_sum_n[tid], sSum[tid]);
        atomicAdd(&g_sq_n[tid], sSq[tid]);
    }
}

// ---- k_node2: out = relu(bn(h_n)) @ w2n + b2n -----------------------------
__global__ __launch_bounds__(128) void k_node2(const float* __restrict__ w2n,
                                               const float* __restrict__ b2n,
                                               float* __restrict__ out, int N) {
    __shared__ __align__(16) float sAT[32 * RS];
    __shared__ __align__(16) float sW[64 * 64];
    const int tid = threadIdx.x, c = tid & 7, r = tid >> 3;
    const int n0 = blockIdx.x * 128;

    for (int idx = tid; idx < 1024; idx += 128) {
        int k = idx >> 4, cq = idx & 15;
        *(float4*)&sW[k * 64 + cq * 4] = *(const float4*)&w2n[k * 64 + cq * 4];
    }
    ull acc[8][4];
#pragma unroll
    for (int i = 0; i < 8; ++i) { acc[i][0] = 0; acc[i][1] = 0; acc[i][2] = 0; acc[i][3] = 0; }

    for (int half = 0; half < 2; ++half) {
        __syncthreads();
#pragma unroll
        for (int it = 0; it < 8; ++it) {
            int idx = tid + it * 128, row = idx >> 3, kq = idx & 7, n = n0 + row;
            float4 v = make_float4(0.f, 0.f, 0.f, 0.f);
            if (n < N) {
                int kb = half * 32 + kq * 4;
                float4 h = *(const float4*)&g_hn[n * 64 + kb];
                float4 a = *(const float4*)&g_an[kb];
                float4 cc = *(const float4*)&g_cn[kb];
                v.x = fmaxf(fmaf(a.x, h.x, cc.x), 0.f);
                v.y = fmaxf(fmaf(a.y, h.y, cc.y), 0.f);
                v.z = fmaxf(fmaf(a.z, h.z, cc.z), 0.f);
                v.w = fmaxf(fmaf(a.w, h.w, cc.w), 0.f);
            }
            stageT(sAT, v, row, kq);
        }
        __syncthreads();
        mm32(sAT, sW + half * 2048, r, c, acc);
    }
    const float4 bb0 = *(const float4*)&b2n[8 * c];
    const float4 bb1 = *(const float4*)&b2n[8 * c + 4];
#pragma unroll
    for (int i = 0; i < 8; ++i) {
        int n = n0 + 8 * r + i;
        if (n < N) {
            float h[8];
            unpk(acc[i][0], h[0], h[1]); unpk(acc[i][1], h[2], h[3]);
            unpk(acc[i][2], h[4], h[5]); unpk(acc[i][3], h[6], h[7]);
            *(float4*)&out[n * 64 + 8 * c] =
                make_float4(h[0] + bb0.x, h[1] + bb0.y, h[2] + bb0.z, h[3] + bb0.w);
            *(float4*)&out[n * 64 + 8 * c + 4] =
                make_float4(h[4] + bb1.x, h[5] + bb1.y, h[6] + bb1.z, h[7] + bb1.w);
        }
    }
}

// ------------------------- launch ------------------------------------------
extern "C" void kernel_launch(void* const* d_in, const int* in_sizes, int n_in,
                              void* d_out, int out_size) {
    const float* x       = (const float*)d_in[0];
    const int*   ei      = (const int*)d_in[1];
    const float* ea      = (const float*)d_in[2];
    const float* w1m     = (const float*)d_in[5];
    const float* b1m     = (const float*)d_in[6];
    const float* gamma_m = (const float*)d_in[7];
    const float* beta_m  = (const float*)d_in[8];
    const float* w2m     = (const float*)d_in[9];
    const float* b2m     = (const float*)d_in[10];
    const float* w1n     = (const float*)d_in[11];
    const float* b1n     = (const float*)d_in[12];
    const float* gamma_n = (const float*)d_in[13];
    const float* beta_n  = (const float*)d_in[14];
    const float* w2n     = (const float*)d_in[15];
    const float* b2n     = (const float*)d_in[16];
    float* out = (float*)d_out;

    const int N = in_sizes[0] / 64;
    const int E = in_sizes[2] / 64;
    const int nb = (N + 127) / 128;
    const int ntiles = (E + 255) / 256;
    const int grid_e = ntiles < 444 ? ntiles : 444;

    k_zero<<<(N * 16 + 255) / 256, 256>>>(N);
    k_wc<<<1, 256>>>(w2m, w1n, b2m);
    k_px<<<nb, 128>>>(x, w1m, N);
    k_edgeA<<<grid_e, 256, SMEM_EA>>>(ea, ei, w1m, b1m, E, ntiles);
    k_bnm<<<1, 64>>>(gamma_m, beta_m, 1.f / (float)E);
    k_edgeB<<<(E * 16 + 255) / 256, 256>>>(ei, E);
    k_node1<<<nb, 128>>>(x, w1n, b1n, N);
    k_bnn<<<1, 64>>>(gamma_n, beta_n, 1.f / (float)N);
    k_node2<<<nb, 128>>>(w2n, b2n, out, N);
}

// round 10
// speedup vs baseline: 1.4578x; 1.1258x over previous
#include <cuda_runtime.h>
#include <cuda_bf16.h>
#include <cuda_fp16.h>
#include <cstdint>

#define NMAX 50000
#define EMAX 800000
#define RS 132  // FFMA2 tile row stride (128 + 4 pad)

typedef unsigned long long ull;

// ------------------------- static device scratch ---------------------------
__device__ __align__(16) float  g_px[NMAX * 64];          // x @ w1m_top
__device__ __align__(16) __half g_h16[(size_t)EMAX * 64]; // edge pre-BN acts (fp16)
__device__ __align__(16) float  g_hn[NMAX * 64];          // node pre-BN acts
__device__ __align__(16) __half g_S16[NMAX * 64];         // scattered relu sums (fp16)
__device__ float  g_cnt[NMAX];
__device__ float  g_sum_m[64], g_sq_m[64], g_sum_n[64], g_sq_n[64];
__device__ __align__(16) float g_am[64], g_cm[64], g_an[64], g_cn[64];
__device__ __align__(16) float g_Wc[64 * 64];             // w2m @ w1n_bot
__device__ __align__(16) float g_bvec[64];                // b2m @ w1n_bot

// ------------------------- bit-cast helpers --------------------------------
__device__ __forceinline__ uint32_t h2u(__half2 h) {
    return *reinterpret_cast<uint32_t*>(&h);
}
__device__ __forceinline__ __half2 u2h(uint32_t u) {
    return *reinterpret_cast<__half2*>(&u);
}

// ------------------------- f32x2 packed FMA helpers ------------------------
__device__ __forceinline__ ull pk2(float x) {
    ull r; asm("mov.b64 %0, {%1, %1};" : "=l"(r) : "f"(x)); return r;
}
__device__ __forceinline__ void fma2(ull& d, ull a, ull b) {
    asm("fma.rn.f32x2 %0, %1, %2, %0;" : "+l"(d) : "l"(a), "l"(b));
}
__device__ __forceinline__ void unpk(ull v, float& lo, float& hi) {
    asm("mov.b64 {%0, %1}, %2;" : "=f"(lo), "=f"(hi) : "l"(v));
}

// ------------------------- mma.sync helpers --------------------------------
__device__ __forceinline__ uint32_t smem_u32(const void* p) {
    uint32_t a;
    asm("{ .reg .u64 t; cvta.to.shared.u64 t, %1; cvt.u32.u64 %0, t; }"
        : "=r"(a) : "l"(p));
    return a;
}

#define LDSM4(R, ADDR) \
    asm volatile("ldmatrix.sync.aligned.m8n8.x4.shared.b16 {%0,%1,%2,%3}, [%4];" \
        : "=r"((R)[0]), "=r"((R)[1]), "=r"((R)[2]), "=r"((R)[3]) : "r"(ADDR))

#define MMA_F16(D, A, B0, B1) \
    asm volatile("mma.sync.aligned.m16n8k16.row.col.f32.f16.f16.f32 " \
        "{%0,%1,%2,%3}, {%4,%5,%6,%7}, {%8,%9}, {%0,%1,%2,%3};" \
        : "+f"((D)[0]), "+f"((D)[1]), "+f"((D)[2]), "+f"((D)[3]) \
        : "r"((A)[0]), "r"((A)[1]), "r"((A)[2]), "r"((A)[3]), "r"(B0), "r"(B1))

// smem layout for k_edgeA (dynamic): total 47616 B
// fp16 tiles use row stride 72 halves = 144 B (ldmatrix conflict-free).
#define OFF_B    0        // 64 x 72 fp16 = 9216
#define OFF_SEND 9216     // int[256]   = 1024
#define OFF_RED  10240    // float[128] = 512
#define OFF_AH   10752    // 256 x 72 fp16 = 36864 (ends 47616)
#define OFF_HS   10752    // reused after MMA: 256 x 72 fp16 staging
#define SMEM_EA  47616

// ------------------------- FFMA2 GEMM tile core (node kernels) -------------
__device__ __forceinline__ void stageT(float* sAT, float4 v, int row, int kq) {
    sAT[(4 * kq + 0) * RS + row] = v.x;
    sAT[(4 * kq + 1) * RS + row] = v.y;
    sAT[(4 * kq + 2) * RS + row] = v.z;
    sAT[(4 * kq + 3) * RS + row] = v.w;
}
__device__ __forceinline__ void mm32(const float* sAT, const float* sW,
                                     int r, int c, ull acc[8][4]) {
#pragma unroll 4
    for (int k = 0; k < 32; ++k) {
        const float4 A0 = *(const float4*)(sAT + k * RS + 8 * r);
        const float4 A1 = *(const float4*)(sAT + k * RS + 8 * r + 4);
        const ulonglong2 Bv0 = *(const ulonglong2*)(sW + k * 64 + 8 * c);
        const ulonglong2 Bv1 = *(const ulonglong2*)(sW + k * 64 + 8 * c + 4);
        float av[8] = {A0.x, A0.y, A0.z, A0.w, A1.x, A1.y, A1.z, A1.w};
#pragma unroll
        for (int i = 0; i < 8; ++i) {
            ull Ad = pk2(av[i]);
            fma2(acc[i][0], Ad, Bv0.x);
            fma2(acc[i][1], Ad, Bv0.y);
            fma2(acc[i][2], Ad, Bv1.x);
            fma2(acc[i][3], Ad, Bv1.y);
        }
    }
}

// ------------------------- k_zero ------------------------------------------
__global__ void k_zero(int N) {
    int i = blockIdx.x * blockDim.x + threadIdx.x;
    if (i < N * 8) ((uint4*)g_S16)[i] = make_uint4(0u, 0u, 0u, 0u);
    if (i < N) g_cnt[i] = 0.f;
    if (i < 64) { g_sum_m[i] = 0.f; g_sq_m[i] = 0.f; g_sum_n[i] = 0.f; g_sq_n[i] = 0.f; }
}

// ------------------------- k_wc: Wc = w2m @ w1n_bot ------------------------
__global__ void k_wc(const float* __restrict__ w2m, const float* __restrict__ w1n,
                     const float* __restrict__ b2m) {
    __shared__ __align__(16) float sB[64 * 64];
    int tid = threadIdx.x;
    for (int idx = tid; idx < 1024; idx += 256) {
        int k = idx >> 4, cq = idx & 15;
        *(float4*)&sB[k * 64 + cq * 4] = *(const float4*)&w1n[(64 + k) * 64 + cq * 4];
    }
    __syncthreads();
    for (int idx = tid; idx < 4096; idx += 256) {
        int i = idx >> 6, j = idx & 63;
        float s = 0.f;
#pragma unroll 8
        for (int k = 0; k < 64; ++k) s += w2m[i * 64 + k] * sB[k * 64 + j];
        g_Wc[idx] = s;
    }
    if (tid < 64) {
        float s = 0.f;
#pragma unroll 8
        for (int k = 0; k < 64; ++k) s += b2m[k] * sB[k * 64 + tid];
        g_bvec[tid] = s;
    }
}

// ------------------------- k_px: px = x @ w1m_top --------------------------
__global__ __launch_bounds__(128) void k_px(const float* __restrict__ x,
                                            const float* __restrict__ w1m, int N) {
    __shared__ __align__(16) float sAT[32 * RS];
    __shared__ __align__(16) float sW[64 * 64];
    const int tid = threadIdx.x, c = tid & 7, r = tid >> 3;
    const int n0 = blockIdx.x * 128;

    for (int idx = tid; idx < 1024; idx += 128) {
        int k = idx >> 4, cq = idx & 15;
        *(float4*)&sW[k * 64 + cq * 4] = *(const float4*)&w1m[k * 64 + cq * 4];
    }
    ull acc[8][4];
#pragma unroll
    for (int i = 0; i < 8; ++i) { acc[i][0] = 0; acc[i][1] = 0; acc[i][2] = 0; acc[i][3] = 0; }

    for (int half = 0; half < 2; ++half) {
        __syncthreads();
#pragma unroll
        for (int it = 0; it < 8; ++it) {
            int idx = tid + it * 128, row = idx >> 3, kq = idx & 7, n = n0 + row;
            float4 v = make_float4(0.f, 0.f, 0.f, 0.f);
            if (n < N) v = *(const float4*)&x[n * 64 + half * 32 + kq * 4];
            stageT(sAT, v, row, kq);
        }
        __syncthreads();
        mm32(sAT, sW + half * 2048, r, c, acc);
    }
#pragma unroll
    for (int i = 0; i < 8; ++i) {
        int n = n0 + 8 * r + i;
        if (n < N) {
            float h[8];
            unpk(acc[i][0], h[0], h[1]); unpk(acc[i][1], h[2], h[3]);
            unpk(acc[i][2], h[4], h[5]); unpk(acc[i][3], h[6], h[7]);
            *(float4*)&g_px[n * 64 + 8 * c]     = make_float4(h[0], h[1], h[2], h[3]);
            *(float4*)&g_px[n * 64 + 8 * c + 4] = make_float4(h[4], h[5], h[6], h[7]);
        }
    }
}

// ---- k_edgeA: fp16 HMMA GEMM (256-row tiles, 512 thr) + px gather ---------
// 16 warps; warp w owns M-strip [16w, 16w+16). acc = 32 regs/thread.
__global__ __launch_bounds__(512, 2) void k_edgeA(const float* __restrict__ ea,
                                                  const int* __restrict__ ei,
                                                  const float* __restrict__ w1m,
                                                  const float* __restrict__ b1m,
                                                  int E, int ntiles) {
    extern __shared__ __align__(1024) char smem[];
    const uint32_t sb = smem_u32(smem);
    const int tid = threadIdx.x, wid = tid >> 5, lane = tid & 31;
    int* sSend = (int*)(smem + OFF_SEND);
    float* sRed = (float*)(smem + OFF_RED);

    // stage B fp16: B[n][k] = w1m[64+k][n], stride 72 halves — once
    for (int idx = tid; idx < 1024; idx += 512) {
        int n = idx & 63, k4 = (idx >> 6) * 4;
        __half2 h01 = __floats2half2_rn(w1m[4096 + (k4 + 0) * 64 + n],
                                        w1m[4096 + (k4 + 1) * 64 + n]);
        __half2 h23 = __floats2half2_rn(w1m[4096 + (k4 + 2) * 64 + n],
                                        w1m[4096 + (k4 + 3) * 64 + n]);
        *(uint2*)(smem + OFF_B + n * 144 + k4 * 2) = make_uint2(h2u(h01), h2u(h23));
    }
    if (tid < 128) sRed[tid] = 0.f;

    const int q = tid & 15;
    const float4 bq = __ldg((const float4*)b1m + q);
    float4 s  = make_float4(0.f, 0.f, 0.f, 0.f);
    float4 s2 = make_float4(0.f, 0.f, 0.f, 0.f);

    // ldmatrix fragment addresses (16-row A strip per warp)
    const int r8 = lane & 7, sel = lane >> 3;
    const uint32_t aBase = sb + (uint32_t)(OFF_AH + (wid * 16 + r8 + (sel & 1) * 8) * 144
                                           + ((sel >> 1) * 8) * 2);
    const uint32_t bBase = sb + (uint32_t)(OFF_B + (((sel >> 1) * 8) + r8) * 144
                                           + ((sel & 1) * 8) * 2);
    const int row0 = lane >> 2, c0 = (lane & 3) * 2;

    for (int t = blockIdx.x; t < ntiles; t += gridDim.x) {
        const int e0 = t * 256;
        __syncthreads();  // guard smem reuse across tiles
        if (tid < 256) { int e = e0 + tid; sSend[tid] = (e < E) ? ei[e] : 0; }

        // stage A fp16 (zero-padded): 256 rows x 16 quads, 8 iters
#pragma unroll
        for (int it = 0; it < 8; ++it) {
            int idx = tid + it * 512, row = idx >> 4, kq = idx & 15;
            float4 v = make_float4(0.f, 0.f, 0.f, 0.f);
            if (e0 + row < E) v = *(const float4*)&ea[(size_t)(e0 + row) * 64 + kq * 4];
            *(uint2*)(smem + OFF_AH + row * 144 + kq * 8) =
                make_uint2(h2u(__floats2half2_rn(v.x, v.y)),
                           h2u(__floats2half2_rn(v.z, v.w)));
        }
        __syncthreads();

        // MMA: D = A @ B (fp16 in, fp32 acc). 32 MMAs/warp.
        float acc[8][4];
#pragma unroll
        for (int nt = 0; nt < 8; ++nt)
#pragma unroll
            for (int j = 0; j < 4; ++j) acc[nt][j] = 0.f;

#pragma unroll
        for (int kt = 0; kt < 4; ++kt) {
            uint32_t aF[4];
            LDSM4(aF, aBase + kt * 32);
#pragma unroll
            for (int nt2 = 0; nt2 < 4; ++nt2) {
                uint32_t bF[4];
                LDSM4(bF, bBase + nt2 * 2304 + kt * 32);
                MMA_F16(acc[2 * nt2],     aF, bF[0], bF[1]);
                MMA_F16(acc[2 * nt2 + 1], aF, bF[2], bF[3]);
            }
        }
        __syncthreads();  // A tile dead -> HS may overwrite

        // stage acc as fp16 into HS
        {
            int rb = wid * 16 + row0;
#pragma unroll
            for (int nt = 0; nt < 8; ++nt) {
                *(__half2*)(smem + OFF_HS + rb * 144 + (8 * nt + c0) * 2) =
                    __floats2half2_rn(acc[nt][0], acc[nt][1]);
                *(__half2*)(smem + OFF_HS + (rb + 8) * 144 + (8 * nt + c0) * 2) =
                    __floats2half2_rn(acc[nt][2], acc[nt][3]);
            }
        }
        __syncthreads();

        // epilogue: h = gemm + px[send] + b1m ; write fp16 h ; stats
#pragma unroll
        for (int it = 0; it < 8; ++it) {
            int row = (tid >> 4) + it * 32;
            int e = e0 + row;
            if (e < E) {
                int snd = sSend[row];
                float4 p = __ldg((const float4*)g_px + snd * 16 + q);
                uint2 g = *(uint2*)(smem + OFF_HS + row * 144 + q * 8);
                float2 f01 = __half22float2(u2h(g.x));
                float2 f23 = __half22float2(u2h(g.y));
                float h0 = f01.x + p.x + bq.x, h1 = f01.y + p.y + bq.y;
                float h2 = f23.x + p.z + bq.z, h3 = f23.y + p.w + bq.w;
                s.x += h0; s.y += h1; s.z += h2; s.w += h3;
                s2.x += h0 * h0; s2.y += h1 * h1; s2.z += h2 * h2; s2.w += h3 * h3;
                *(uint2*)&g_h16[(size_t)e * 64 + q * 4] =
                    make_uint2(h2u(__floats2half2_rn(h0, h1)),
                               h2u(__floats2half2_rn(h2, h3)));
            }
        }
    }

    // flush BN stats
    __syncthreads();
    atomicAdd(&sRed[q * 4 + 0], s.x);  atomicAdd(&sRed[q * 4 + 1], s.y);
    atomicAdd(&sRed[q * 4 + 2], s.z);  atomicAdd(&sRed[q * 4 + 3], s.w);
    atomicAdd(&sRed[64 + q * 4 + 0], s2.x); atomicAdd(&sRed[64 + q * 4 + 1], s2.y);
    atomicAdd(&sRed[64 + q * 4 + 2], s2.z); atomicAdd(&sRed[64 + q * 4 + 3], s2.w);
    __syncthreads();
    if (tid < 64) {
        atomicAdd(&g_sum_m[tid], sRed[tid]);
        atomicAdd(&g_sq_m[tid], sRed[64 + tid]);
    }
}

// ------------------------- BN coefficient kernels --------------------------
__global__ void k_bnm(const float* __restrict__ gamma, const float* __restrict__ beta,
                      float inv) {
    int j = threadIdx.x;
    float mu = g_sum_m[j] * inv;
    float var = g_sq_m[j] * inv - mu * mu;
    float a = gamma[j] * rsqrtf(var + 1e-5f);
    g_am[j] = a; g_cm[j] = beta[j] - mu * a;
}
__global__ void k_bnn(const float* __restrict__ gamma, const float* __restrict__ beta,
                      float inv) {
    int j = threadIdx.x;
    float mu = g_sum_n[j] * inv;
    float var = g_sq_n[j] * inv - mu * mu;
    float a = gamma[j] * rsqrtf(var + 1e-5f);
    g_an[j] = a; g_cn[j] = beta[j] - mu * a;
}

// ---- k_edgeB: relu(bn(h16)) scatter-add (fp16 v4 reductions) --------------
// One thread per (edge, 8-col group): 8 ops/edge instead of 16.
__global__ __launch_bounds__(256) void k_edgeB(const int* __restrict__ ei, int E) {
    int idx = blockIdx.x * 256 + threadIdx.x;
    if (idx >= E * 8) return;
    int e = idx >> 3, g = idx & 7;
    uint4 hv = *(const uint4*)&g_h16[(size_t)e * 64 + g * 8];
    float4 a0 = *(const float4*)&g_am[g * 8];
    float4 a1 = *(const float4*)&g_am[g * 8 + 4];
    float4 c0 = *(const float4*)&g_cm[g * 8];
    float4 c1 = *(const float4*)&g_cm[g * 8 + 4];
    float2 f0 = __half22float2(u2h(hv.x));
    float2 f1 = __half22float2(u2h(hv.y));
    float2 f2 = __half22float2(u2h(hv.z));
    float2 f3 = __half22float2(u2h(hv.w));
    float v0 = fmaxf(fmaf(a0.x, f0.x, c0.x), 0.f);
    float v1 = fmaxf(fmaf(a0.y, f0.y, c0.y), 0.f);
    float v2 = fmaxf(fmaf(a0.z, f1.x, c0.z), 0.f);
    float v3 = fmaxf(fmaf(a0.w, f1.y, c0.w), 0.f);
    float v4 = fmaxf(fmaf(a1.x, f2.x, c1.x), 0.f);
    float v5 = fmaxf(fmaf(a1.y, f2.y, c1.y), 0.f);
    float v6 = fmaxf(fmaf(a1.z, f3.x, c1.z), 0.f);
    float v7 = fmaxf(fmaf(a1.w, f3.y, c1.w), 0.f);
    uint32_t p0 = h2u(__floats2half2_rn(v0, v1));
    uint32_t p1 = h2u(__floats2half2_rn(v2, v3));
    uint32_t p2 = h2u(__floats2half2_rn(v4, v5));
    uint32_t p3 = h2u(__floats2half2_rn(v6, v7));
    int rec = ei[E + e];
    __half* dst = &g_S16[rec * 64 + g * 8];
    asm volatile("red.global.add.noftz.v4.f16x2 [%0], {%1,%2,%3,%4};"
                 :: "l"(dst), "r"(p0), "r"(p1), "r"(p2), "r"(p3) : "memory");
    if (g == 0) atomicAdd(&g_cnt[rec], 1.f);
}

// ---- k_node1: h_n = x@w1n_top + (S/cnt')@Wc + b1n + [cnt>0]*bvec ----------
__global__ __launch_bounds__(128) void k_node1(const float* __restrict__ x,
                                               const float* __restrict__ w1n,
                                               const float* __restrict__ b1n, int N) {
    __shared__ __align__(16) float sAT[32 * RS];
    __shared__ __align__(16) float sW[64 * 64];
    __shared__ float sSum[64], sSq[64];
    const int tid = threadIdx.x, c = tid & 7, r = tid >> 3;
    const int n0 = blockIdx.x * 128;
    if (tid < 64) { sSum[tid] = 0.f; sSq[tid] = 0.f; }

    ull acc[8][4];
#pragma unroll
    for (int i = 0; i < 8; ++i) { acc[i][0] = 0; acc[i][1] = 0; acc[i][2] = 0; acc[i][3] = 0; }

    for (int ph = 0; ph < 2; ++ph) {
        __syncthreads();
        for (int idx = tid; idx < 1024; idx += 128) {
            int k = idx >> 4, cq = idx & 15;
            *(float4*)&sW[k * 64 + cq * 4] = (ph == 0)
                ? *(const float4*)&w1n[k * 64 + cq * 4]
                : *(const float4*)&g_Wc[k * 64 + cq * 4];
        }
        for (int half = 0; half < 2; ++half) {
            __syncthreads();
#pragma unroll
            for (int it = 0; it < 8; ++it) {
                int idx = tid + it * 128, row = idx >> 3, kq = idx & 7, n = n0 + row;
                float4 v = make_float4(0.f, 0.f, 0.f, 0.f);
                if (n < N) {
                    if (ph == 0) {
                        v = *(const float4*)&x[n * 64 + half * 32 + kq * 4];
                    } else {
                        uint2 gg = *(const uint2*)&g_S16[n * 64 + half * 32 + kq * 4];
                        float2 s01 = __half22float2(u2h(gg.x));
                        float2 s23 = __half22float2(u2h(gg.y));
                        float inv = 1.f / fmaxf(g_cnt[n], 1.f);
                        v = make_float4(s01.x * inv, s01.y * inv, s23.x * inv, s23.y * inv);
                    }
                }
                stageT(sAT, v, row, kq);
            }
            __syncthreads();
            mm32(sAT, sW + half * 2048, r, c, acc);
        }
    }

    const float4 bb0 = *(const float4*)&b1n[8 * c];
    const float4 bb1 = *(const float4*)&b1n[8 * c + 4];
    const float4 bv0 = *(const float4*)&g_bvec[8 * c];
    const float4 bv1 = *(const float4*)&g_bvec[8 * c + 4];
    float ls[8], lq[8];
#pragma unroll
    for (int j = 0; j < 8; ++j) { ls[j] = 0.f; lq[j] = 0.f; }

#pragma unroll
    for (int i = 0; i < 8; ++i) {
        int n = n0 + 8 * r + i;
        if (n < N) {
            float ind = (g_cnt[n] > 0.f) ? 1.f : 0.f;
            float h[8];
            unpk(acc[i][0], h[0], h[1]); unpk(acc[i][1], h[2], h[3]);
            unpk(acc[i][2], h[4], h[5]); unpk(acc[i][3], h[6], h[7]);
            h[0] += bb0.x + ind * bv0.x; h[1] += bb0.y + ind * bv0.y;
            h[2] += bb0.z + ind * bv0.z; h[3] += bb0.w + ind * bv0.w;
            h[4] += bb1.x + ind * bv1.x; h[5] += bb1.y + ind * bv1.y;
            h[6] += bb1.z + ind * bv1.z; h[7] += bb1.w + ind * bv1.w;
            *(float4*)&g_hn[n * 64 + 8 * c]     = make_float4(h[0], h[1], h[2], h[3]);
            *(float4*)&g_hn[n * 64 + 8 * c + 4] = make_float4(h[4], h[5], h[6], h[7]);
#pragma unroll
            for (int j = 0; j < 8; ++j) { ls[j] += h[j]; lq[j] += h[j] * h[j]; }
        }
    }
#pragma unroll
    for (int j = 0; j < 8; ++j) {
        atomicAdd(&sSum[8 * c + j], ls[j]);
        atomicAdd(&sSq[8 * c + j], lq[j]);
    }
    __syncthreads();
    if (tid < 64) {
        atomicAdd(&g_sum_n[tid], sSum[tid]);
        atomicAdd(&g_sq_n[tid], sSq[tid]);
    }
}

// ---- k_node2: out = relu(bn(h_n)) @ w2n + b2n -----------------------------
__global__ __launch_bounds__(128) void k_node2(const float* __restrict__ w2n,
                                               const float* __restrict__ b2n,
                                               float* __restrict__ out, int N) {
    __shared__ __align__(16) float sAT[32 * RS];
    __shared__ __align__(16) float sW[64 * 64];
    const int tid = threadIdx.x, c = tid & 7, r = tid >> 3;
    const int n0 = blockIdx.x * 128;

    for (int idx = tid; idx < 1024; idx += 128) {
        int k = idx >> 4, cq = idx & 15;
        *(float4*)&sW[k * 64 + cq * 4] = *(const float4*)&w2n[k * 64 + cq * 4];
    }
    ull acc[8][4];
#pragma unroll
    for (int i = 0; i < 8; ++i) { acc[i][0] = 0; acc[i][1] = 0; acc[i][2] = 0; acc[i][3] = 0; }

    for (int half = 0; half < 2; ++half) {
        __syncthreads();
#pragma unroll
        for (int it = 0; it < 8; ++it) {
            int idx = tid + it * 128, row = idx >> 3, kq = idx & 7, n = n0 + row;
            float4 v = make_float4(0.f, 0.f, 0.f, 0.f);
            if (n < N) {
                int kb = half * 32 + kq * 4;
                float4 h = *(const float4*)&g_hn[n * 64 + kb];
                float4 a = *(const float4*)&g_an[kb];
                float4 cc = *(const float4*)&g_cn[kb];
                v.x = fmaxf(fmaf(a.x, h.x, cc.x), 0.f);
                v.y = fmaxf(fmaf(a.y, h.y, cc.y), 0.f);
                v.z = fmaxf(fmaf(a.z, h.z, cc.z), 0.f);
                v.w = fmaxf(fmaf(a.w, h.w, cc.w), 0.f);
            }
            stageT(sAT, v, row, kq);
        }
        __syncthreads();
        mm32(sAT, sW + half * 2048, r, c, acc);
    }
    const float4 bb0 = *(const float4*)&b2n[8 * c];
    const float4 bb1 = *(const float4*)&b2n[8 * c + 4];
#pragma unroll
    for (int i = 0; i < 8; ++i) {
        int n = n0 + 8 * r + i;
        if (n < N) {
            float h[8];
            unpk(acc[i][0], h[0], h[1]); unpk(acc[i][1], h[2], h[3]);
            unpk(acc[i][2], h[4], h[5]); unpk(acc[i][3], h[6], h[7]);
            *(float4*)&out[n * 64 + 8 * c] =
                make_float4(h[0] + bb0.x, h[1] + bb0.y, h[2] + bb0.z, h[3] + bb0.w);
            *(float4*)&out[n * 64 + 8 * c + 4] =
                make_float4(h[4] + bb1.x, h[5] + bb1.y, h[6] + bb1.z, h[7] + bb1.w);
        }
    }
}

// ------------------------- launch ------------------------------------------
extern "C" void kernel_launch(void* const* d_in, const int* in_sizes, int n_in,
                              void* d_out, int out_size) {
    const float* x       = (const float*)d_in[0];
    const int*   ei      = (const int*)d_in[1];
    const float* ea      = (const float*)d_in[2];
    const float* w1m     = (const float*)d_in[5];
    const float* b1m     = (const float*)d_in[6];
    const float* gamma_m = (const float*)d_in[7];
    const float* beta_m  = (const float*)d_in[8];
    const float* w2m     = (const float*)d_in[9];
    const float* b2m     = (const float*)d_in[10];
    const float* w1n     = (const float*)d_in[11];
    const float* b1n     = (const float*)d_in[12];
    const float* gamma_n = (const float*)d_in[13];
    const float* beta_n  = (const float*)d_in[14];
    const float* w2n     = (const float*)d_in[15];
    const float* b2n     = (const float*)d_in[16];
    float* out = (float*)d_out;

    const int N = in_sizes[0] / 64;
    const int E = in_sizes[2] / 64;
    const int nb = (N + 127) / 128;
    const int ntiles = (E + 255) / 256;
    const int grid_e = ntiles < 296 ? ntiles : 296;   // 2 CTAs/SM x 148 SMs

    k_zero<<<(N * 8 + 255) / 256, 256>>>(N);
    k_wc<<<1, 256>>>(w2m, w1n, b2m);
    k_px<<<nb, 128>>>(x, w1m, N);
    k_edgeA<<<grid_e, 512, SMEM_EA>>>(ea, ei, w1m, b1m, E, ntiles);
    k_bnm<<<1, 64>>>(gamma_m, beta_m, 1.f / (float)E);
    k_edgeB<<<(E * 8 + 255) / 256, 256>>>(ei, E);
    k_node1<<<nb, 128>>>(x, w1n, b1n, N);
    k_bnn<<<1, 64>>>(gamma_n, beta_n, 1.f / (float)N);
    k_node2<<<nb, 128>>>(w2n, b2n, out, N);
}